// round 1
// baseline (speedup 1.0000x reference)
#include <cuda_runtime.h>
#include <math.h>

// Problem constants
#define BATCH 4
#define TLEN  1024
#define EDIM  1024
#define HEADS 16
#define SDIM  64
#define P2    2047   // 2*t - 1

// ---------------------------------------------------------------------------
// Scratch (device globals — no runtime allocation allowed)
// ---------------------------------------------------------------------------
__device__ float g_Q  [(size_t)BATCH * TLEN * EDIM];
__device__ float g_K  [(size_t)BATCH * TLEN * EDIM];
__device__ float g_V  [(size_t)BATCH * TLEN * EDIM];
__device__ float g_KP [(size_t)P2 * EDIM];
__device__ float g_dpt[(size_t)BATCH * HEADS * TLEN];
__device__ float g_cpp[(size_t)HEADS * P2];
__device__ float g_ATT[(size_t)BATCH * TLEN * EDIM];

// ---------------------------------------------------------------------------
// SGEMM: C[M,N] = A[M,K] @ B[K,N] (+ bias), all row-major fp32.
// 128x128 block tile, BK=8, 256 threads, 8x8 microtile, pipelined loads.
// ---------------------------------------------------------------------------
__global__ void __launch_bounds__(256) sgemm_kernel(
    const float* __restrict__ A, const float* __restrict__ Bm,
    const float* __restrict__ bias, float* __restrict__ C,
    int M, int N, int Kd, int hasBias)
{
    __shared__ float As[8][128];   // transposed A tile: As[k][row]
    __shared__ float Bs[8][128];   // Bs[k][col]

    const int tid = threadIdx.x;
    const int bm = blockIdx.y * 128;
    const int bn = blockIdx.x * 128;
    const int tx = tid & 15, ty = tid >> 4;

    const int ar = tid >> 1;          // A tile row 0..127
    const int ak = (tid & 1) * 4;     // A tile k   0 or 4
    const int br = tid >> 5;          // B tile k   0..7
    const int bc = (tid & 31) * 4;    // B tile col 0..124

    const bool aV = (bm + ar) < M;
    const float* Ap = A + (size_t)(bm + ar) * Kd + ak;
    const float* Bp = Bm + (size_t)br * N + bn + bc;

    float4 av = aV ? *(const float4*)Ap : make_float4(0.f, 0.f, 0.f, 0.f);
    float4 bv = *(const float4*)Bp;

    float acc[8][8] = {};

    const int nk = Kd >> 3;
    for (int kt = 0; kt < nk; kt++) {
        __syncthreads();
        As[ak + 0][ar] = av.x;
        As[ak + 1][ar] = av.y;
        As[ak + 2][ar] = av.z;
        As[ak + 3][ar] = av.w;
        *(float4*)&Bs[br][bc] = bv;
        __syncthreads();
        if (kt + 1 < nk) {   // prefetch next tile (overlaps with compute)
            Ap += 8;
            Bp += (size_t)8 * N;
            av = aV ? *(const float4*)Ap : make_float4(0.f, 0.f, 0.f, 0.f);
            bv = *(const float4*)Bp;
        }
        #pragma unroll
        for (int k = 0; k < 8; k++) {
            float a[8], b[8];
            #pragma unroll
            for (int i = 0; i < 8; i++) a[i] = As[k][ty + 16 * i];
            #pragma unroll
            for (int j = 0; j < 8; j++) b[j] = Bs[k][tx + 16 * j];
            #pragma unroll
            for (int i = 0; i < 8; i++)
                #pragma unroll
                for (int j = 0; j < 8; j++)
                    acc[i][j] = fmaf(a[i], b[j], acc[i][j]);
        }
    }

    #pragma unroll
    for (int i = 0; i < 8; i++) {
        int row = bm + ty + 16 * i;
        if (row < M) {
            #pragma unroll
            for (int j = 0; j < 8; j++) {
                int col = bn + tx + 16 * j;
                float v = acc[i][j];
                if (hasBias) v += bias[col];
                C[(size_t)row * N + col] = v;
            }
        }
    }
}

// ---------------------------------------------------------------------------
// dpt[b,h,j] = sum_s parma[h,s] * K[b, j, h*64+s]
// ---------------------------------------------------------------------------
__global__ void __launch_bounds__(256) dpt_kernel(
    const float* __restrict__ Kt, const float* __restrict__ parma,
    float* __restrict__ dpt)
{
    int idx = blockIdx.x * 256 + threadIdx.x;     // b*H*T + h*T + j
    if (idx >= BATCH * HEADS * TLEN) return;
    int j = idx & (TLEN - 1);
    int h = (idx >> 10) & (HEADS - 1);
    int b = idx >> 14;
    const float* kr = Kt + ((size_t)(b * TLEN + j)) * EDIM + h * SDIM;
    const float* pa = parma + h * SDIM;
    float s = 0.f;
    #pragma unroll
    for (int ss = 0; ss < SDIM; ss++) s = fmaf(pa[ss], kr[ss], s);
    dpt[idx] = s;
}

// ---------------------------------------------------------------------------
// cpp[h,p] = sum_s parmb[h,s] * KP[p, h*64+s]
// ---------------------------------------------------------------------------
__global__ void __launch_bounds__(256) cpp_kernel(
    const float* __restrict__ KP, const float* __restrict__ parmb,
    float* __restrict__ cpp)
{
    int idx = blockIdx.x * 256 + threadIdx.x;     // h*P2 + p
    if (idx >= HEADS * P2) return;
    int h = idx / P2;
    int p = idx - h * P2;
    const float* kr = KP + (size_t)p * EDIM + h * SDIM;
    const float* pb = parmb + h * SDIM;
    float s = 0.f;
    #pragma unroll
    for (int ss = 0; ss < SDIM; ss++) s = fmaf(pb[ss], kr[ss], s);
    cpp[idx] = s;
}

// ---------------------------------------------------------------------------
// Attention: one CTA per (b, h, 64-row i-tile); causal loop over 64-col j-tiles.
// scores(i,j) = q_i . (k_j + kp_{i+j}) + dpt[j] + cpp[i+j]; online softmax; P@V.
// ---------------------------------------------------------------------------
#define ATTN_SMEM_FLOATS (64*65 + 64*65 + 64*64 + 64*129 + 64 + 128)

__global__ void __launch_bounds__(256) attn_kernel(
    const float* __restrict__ Q, const float* __restrict__ Kt,
    const float* __restrict__ V, const float* __restrict__ KP,
    const float* __restrict__ dpt, const float* __restrict__ cpp,
    float* __restrict__ O)
{
    extern __shared__ float sm[];
    float* Qs   = sm;                 // [s=64][r=64] pad 65
    float* Ks   = Qs + 64 * 65;      // [s=64][c=64] pad 65
    float* Vs   = Ks + 64 * 65;      // [j=64][s=64]
    float* KPs  = Vs + 64 * 64;      // [s=64][p_local=128] pad 129 (unioned with Ps)
    float* Ps   = KPs;               // [r=64][c=64] pad 65 (reuse after scores done)
    float* dpts = KPs + 64 * 129;    // [64]
    float* cpps = dpts + 64;         // [128]

    const int tid = threadIdx.x;
    const int tx = tid & 15, ty = tid >> 4;
    const int b = blockIdx.z, h = blockIdx.y;
    const int it = (int)gridDim.x - 1 - (int)blockIdx.x;  // big tiles first
    const int I0 = it * 64;
    const size_t headOff = (size_t)h * SDIM;

    // Q tile (transposed)
    for (int idx = tid; idx < 4096; idx += 256) {
        int r = idx >> 6, s = idx & 63;
        Qs[s * 65 + r] = Q[((size_t)(b * TLEN + I0 + r)) * EDIM + headOff + s];
    }

    float m_r[4], l_r[4], o[4][4];
    #pragma unroll
    for (int i = 0; i < 4; i++) {
        m_r[i] = -INFINITY;
        l_r[i] = 0.f;
        #pragma unroll
        for (int j = 0; j < 4; j++) o[i][j] = 0.f;
    }

    for (int jt = 0; jt <= it; jt++) {
        const int J0 = jt * 64;
        const int pbase = I0 + J0;

        // Stage K (transposed), V (natural), KP band (transposed), dpt, cpp
        for (int idx = tid; idx < 4096; idx += 256) {
            int c = idx >> 6, s = idx & 63;
            size_t g = ((size_t)(b * TLEN + J0 + c)) * EDIM + headOff + s;
            Ks[s * 65 + c] = Kt[g];
            Vs[c * 64 + s] = V[g];
        }
        for (int idx = tid; idx < 8192; idx += 256) {
            int pl = idx >> 6, s = idx & 63;
            int p = pbase + pl;
            KPs[s * 129 + pl] = (p < P2) ? KP[(size_t)p * EDIM + headOff + s] : 0.f;
        }
        if (tid < 64) dpts[tid] = dpt[((size_t)(b * HEADS + h)) * TLEN + J0 + tid];
        if (tid < 128) {
            int p = pbase + tid;
            cpps[tid] = (p < P2) ? cpp[(size_t)h * P2 + p] : 0.f;
        }
        __syncthreads();

        // Scores: acc[i][j] = sum_s q[r_i][s] * (k[c_j][s] + kp[r_i+c_j][s])
        float acc[4][4];
        #pragma unroll
        for (int i = 0; i < 4; i++)
            #pragma unroll
            for (int j = 0; j < 4; j++) acc[i][j] = 0.f;

        #pragma unroll 4
        for (int s = 0; s < 64; s++) {
            float a[4], bk[4], kpv[7];
            #pragma unroll
            for (int i = 0; i < 4; i++) a[i] = Qs[s * 65 + ty + 16 * i];
            #pragma unroll
            for (int j = 0; j < 4; j++) bk[j] = Ks[s * 65 + tx + 16 * j];
            #pragma unroll
            for (int d = 0; d < 7; d++) kpv[d] = KPs[s * 129 + ty + tx + 16 * d];
            #pragma unroll
            for (int i = 0; i < 4; i++)
                #pragma unroll
                for (int j = 0; j < 4; j++)
                    acc[i][j] = fmaf(a[i], bk[j] + kpv[i + j], acc[i][j]);
        }

        // Bias terms + causal mask + online softmax (row group = 16 lanes)
        #pragma unroll
        for (int i = 0; i < 4; i++) {
            int r = ty + 16 * i;
            float mx = -INFINITY;
            float sc[4];
            #pragma unroll
            for (int j = 0; j < 4; j++) {
                int c = tx + 16 * j;
                float v = acc[i][j] + dpts[c] + cpps[r + c];
                if (J0 + c > I0 + r) v = -1e30f;
                sc[j] = v;
                mx = fmaxf(mx, v);
            }
            #pragma unroll
            for (int off = 8; off >= 1; off >>= 1)
                mx = fmaxf(mx, __shfl_xor_sync(0xffffffffu, mx, off));
            float mnew = fmaxf(m_r[i], mx);
            float scale = __expf(m_r[i] - mnew);
            m_r[i] = mnew;
            float rs = 0.f;
            #pragma unroll
            for (int j = 0; j < 4; j++) {
                float p = __expf(sc[j] - mnew);
                acc[i][j] = p;
                rs += p;
            }
            #pragma unroll
            for (int off = 8; off >= 1; off >>= 1)
                rs += __shfl_xor_sync(0xffffffffu, rs, off);
            l_r[i] = l_r[i] * scale + rs;
            #pragma unroll
            for (int j2 = 0; j2 < 4; j2++) o[i][j2] *= scale;
        }

        __syncthreads();   // everyone done reading KPs before Ps overwrite
        #pragma unroll
        for (int i = 0; i < 4; i++)
            #pragma unroll
            for (int j = 0; j < 4; j++)
                Ps[(ty + 16 * i) * 65 + tx + 16 * j] = acc[i][j];
        __syncthreads();

        // O += P @ V   (thread owns rows r_i, output dims tx+16*j2)
        for (int jj = 0; jj < 64; jj++) {
            float vv[4];
            #pragma unroll
            for (int j2 = 0; j2 < 4; j2++) vv[j2] = Vs[jj * 64 + tx + 16 * j2];
            #pragma unroll
            for (int i = 0; i < 4; i++) {
                float p = Ps[(ty + 16 * i) * 65 + jj];
                #pragma unroll
                for (int j2 = 0; j2 < 4; j2++)
                    o[i][j2] = fmaf(p, vv[j2], o[i][j2]);
            }
        }
        __syncthreads();   // before next tile overwrites Ks/Vs/KPs
    }

    #pragma unroll
    for (int i = 0; i < 4; i++) {
        float inv = 1.f / l_r[i];
        int r = I0 + ty + 16 * i;
        #pragma unroll
        for (int j2 = 0; j2 < 4; j2++)
            O[((size_t)(b * TLEN + r)) * EDIM + headOff + tx + 16 * j2] = o[i][j2] * inv;
    }
}

// ---------------------------------------------------------------------------
// Launch
// ---------------------------------------------------------------------------
extern "C" void kernel_launch(void* const* d_in, const int* in_sizes, int n_in,
                              void* d_out, int out_size)
{
    const float* x     = (const float*)d_in[0];
    const float* Wq    = (const float*)d_in[1];
    const float* Wk    = (const float*)d_in[2];
    const float* Wkp   = (const float*)d_in[3];
    const float* Wv    = (const float*)d_in[4];
    const float* Wu    = (const float*)d_in[5];
    const float* bu    = (const float*)d_in[6];
    const float* parma = (const float*)d_in[7];
    const float* parmb = (const float*)d_in[8];
    const float* pos   = (const float*)d_in[9];
    float* out = (float*)d_out;

    float *Qb, *Kb, *Vb, *KPb, *dptb, *cppb, *ATTb;
    cudaGetSymbolAddress((void**)&Qb,   g_Q);
    cudaGetSymbolAddress((void**)&Kb,   g_K);
    cudaGetSymbolAddress((void**)&Vb,   g_V);
    cudaGetSymbolAddress((void**)&KPb,  g_KP);
    cudaGetSymbolAddress((void**)&dptb, g_dpt);
    cudaGetSymbolAddress((void**)&cppb, g_cpp);
    cudaGetSymbolAddress((void**)&ATTb, g_ATT);

    dim3 blk(256);
    dim3 g1(EDIM / 128, (BATCH * TLEN) / 128);   // (8, 32)
    sgemm_kernel<<<g1, blk>>>(x, Wq, nullptr, Qb, BATCH * TLEN, EDIM, EDIM, 0);
    sgemm_kernel<<<g1, blk>>>(x, Wk, nullptr, Kb, BATCH * TLEN, EDIM, EDIM, 0);
    sgemm_kernel<<<g1, blk>>>(x, Wv, nullptr, Vb, BATCH * TLEN, EDIM, EDIM, 0);

    dim3 g2(EDIM / 128, (P2 + 127) / 128);       // (8, 16)
    sgemm_kernel<<<g2, blk>>>(pos, Wkp, nullptr, KPb, P2, EDIM, EDIM, 0);

    dpt_kernel<<<(BATCH * HEADS * TLEN) / 256, blk>>>(Kb, parma, dptb);
    cpp_kernel<<<(HEADS * P2 + 255) / 256, blk>>>(KPb, parmb, cppb);

    size_t smemBytes = (size_t)ATTN_SMEM_FLOATS * sizeof(float);
    cudaFuncSetAttribute(attn_kernel,
                         cudaFuncAttributeMaxDynamicSharedMemorySize,
                         (int)smemBytes);
    attn_kernel<<<dim3(TLEN / 64, HEADS, BATCH), blk, smemBytes>>>(
        Qb, Kb, Vb, KPb, dptb, cppb, ATTb);

    sgemm_kernel<<<g1, blk>>>(ATTb, Wu, bu, out, BATCH * TLEN, EDIM, EDIM, 1);
}

// round 3
// speedup vs baseline: 1.3011x; 1.3011x over previous
#include <cuda_runtime.h>
#include <math.h>
#include <stdint.h>

// Problem constants
#define BATCH 4
#define TLEN  1024
#define EDIM  1024
#define HEADS 16
#define SDIM  64
#define P2    2047   // 2*t - 1

// ---------------------------------------------------------------------------
// Scratch (device globals — no runtime allocation allowed)
// ---------------------------------------------------------------------------
__device__ float g_Q  [(size_t)BATCH * TLEN * EDIM];
__device__ float g_K  [(size_t)BATCH * TLEN * EDIM];
__device__ float g_V  [(size_t)BATCH * TLEN * EDIM];
__device__ float g_KP [(size_t)P2 * EDIM];
__device__ float g_dpt[(size_t)BATCH * HEADS * TLEN];
__device__ float g_cpp[(size_t)HEADS * P2];
__device__ float g_ATT[(size_t)BATCH * TLEN * EDIM];
__device__ float g_Wt [(size_t)5 * EDIM * EDIM];   // transposed weights [N,K]

// ---------------------------------------------------------------------------
// tf32 helpers (baseline PTX — no sm_103a-gated instructions)
// ---------------------------------------------------------------------------
__device__ __forceinline__ uint32_t f2tf32(float x) {
    uint32_t r;
    asm("cvt.rna.tf32.f32 %0, %1;" : "=r"(r) : "f"(x));
    return r;
}
__device__ __forceinline__ void split_tf32(float x, uint32_t& hi, uint32_t& lo) {
    hi = f2tf32(x);
    lo = f2tf32(x - __uint_as_float(hi));
}
__device__ __forceinline__ void mma_tf32(float* c,
    uint32_t a0, uint32_t a1, uint32_t a2, uint32_t a3,
    uint32_t b0, uint32_t b1)
{
    asm volatile(
        "mma.sync.aligned.m16n8k8.row.col.f32.tf32.tf32.f32 "
        "{%0,%1,%2,%3}, {%4,%5,%6,%7}, {%8,%9}, {%0,%1,%2,%3};"
        : "+f"(c[0]), "+f"(c[1]), "+f"(c[2]), "+f"(c[3])
        : "r"(a0), "r"(a1), "r"(a2), "r"(a3), "r"(b0), "r"(b1));
}

// ---------------------------------------------------------------------------
// Weight transpose: dst[N,K] = src[K,N], 1024x1024
// ---------------------------------------------------------------------------
__global__ void __launch_bounds__(256) transpose_kernel(
    const float* __restrict__ src, float* __restrict__ dst)
{
    __shared__ float t[32][33];
    int bx = blockIdx.x * 32, by = blockIdx.y * 32;
    int x = threadIdx.x, y = threadIdx.y;   // block (32, 8)
    #pragma unroll
    for (int i = 0; i < 32; i += 8)
        t[y + i][x] = src[(size_t)(by + y + i) * EDIM + bx + x];
    __syncthreads();
    #pragma unroll
    for (int i = 0; i < 32; i += 8)
        dst[(size_t)(bx + y + i) * EDIM + by + x] = t[x][y + i];
}

// ---------------------------------------------------------------------------
// Tensor-core GEMM (tf32x3): C[M,1024] = A[M,1024] @ Bt[1024,1024]^T (+bias)
// 128x128 CTA tile, BK=32, 256 threads (8 warps, each 64m x 32n),
// m16n8k8 tf32 mma with hi/lo error compensation (3 mma per tile pair).
// ---------------------------------------------------------------------------
#define PADK 36

__global__ void __launch_bounds__(256) tc_gemm_kernel(
    const float* __restrict__ A, const float* __restrict__ Bt,
    const float* __restrict__ bias, float* __restrict__ C,
    int M, int hasBias)
{
    __shared__ float As[128][PADK];
    __shared__ float Bs[128][PADK];

    const int tid  = threadIdx.x;
    const int wid  = tid >> 5;
    const int lane = tid & 31;
    const int wm = wid & 1;          // 0..1 : 64-row slice
    const int wn = wid >> 1;         // 0..3 : 32-col slice
    const int g = lane >> 2;         // group id 0..7
    const int t = lane & 3;          // thread-in-group 0..3
    const int bm = blockIdx.y * 128;
    const int bn = blockIdx.x * 128;

    const float4 f4z = make_float4(0.f, 0.f, 0.f, 0.f);
    float4 ra[4], rb[4];

    // prologue: stage k-tile 0 (slot = tid + 256*r; row = slot>>3, kc=(slot&7)*4)
    #pragma unroll
    for (int r = 0; r < 4; r++) {
        int slot = tid + 256 * r;
        int row = slot >> 3, kc = (slot & 7) * 4;
        int grow = bm + row;
        ra[r] = (grow < M) ? *(const float4*)&A[(size_t)grow * EDIM + kc] : f4z;
        rb[r] = *(const float4*)&Bt[(size_t)(bn + row) * EDIM + kc];
    }

    float acc[4][4][4];
    #pragma unroll
    for (int mi = 0; mi < 4; mi++)
        #pragma unroll
        for (int ni = 0; ni < 4; ni++)
            #pragma unroll
            for (int q = 0; q < 4; q++) acc[mi][ni][q] = 0.f;

    #pragma unroll 1
    for (int kt = 0; kt < 32; kt++) {
        __syncthreads();
        #pragma unroll
        for (int r = 0; r < 4; r++) {
            int slot = tid + 256 * r;
            int row = slot >> 3, kc = (slot & 7) * 4;
            *(float4*)&As[row][kc] = ra[r];
            *(float4*)&Bs[row][kc] = rb[r];
        }
        __syncthreads();

        if (kt + 1 < 32) {   // prefetch next k-tile (overlaps mma work)
            int koff = (kt + 1) * 32;
            #pragma unroll
            for (int r = 0; r < 4; r++) {
                int slot = tid + 256 * r;
                int row = slot >> 3, kc = (slot & 7) * 4;
                int grow = bm + row;
                ra[r] = (grow < M) ? *(const float4*)&A[(size_t)grow * EDIM + koff + kc] : f4z;
                rb[r] = *(const float4*)&Bt[(size_t)(bn + row) * EDIM + koff + kc];
            }
        }

        #pragma unroll
        for (int kk = 0; kk < 32; kk += 8) {
            uint32_t ah[4][4], al[4][4], bh[4][2], bl[4][2];
            #pragma unroll
            for (int mi = 0; mi < 4; mi++) {
                int r0 = wm * 64 + mi * 16 + g;
                int c0 = kk + t;
                split_tf32(As[r0][c0],         ah[mi][0], al[mi][0]);
                split_tf32(As[r0 + 8][c0],     ah[mi][1], al[mi][1]);
                split_tf32(As[r0][c0 + 4],     ah[mi][2], al[mi][2]);
                split_tf32(As[r0 + 8][c0 + 4], ah[mi][3], al[mi][3]);
            }
            #pragma unroll
            for (int ni = 0; ni < 4; ni++) {
                int rn = wn * 32 + ni * 8 + g;
                split_tf32(Bs[rn][kk + t],     bh[ni][0], bl[ni][0]);
                split_tf32(Bs[rn][kk + t + 4], bh[ni][1], bl[ni][1]);
            }
            #pragma unroll
            for (int mi = 0; mi < 4; mi++)
                #pragma unroll
                for (int ni = 0; ni < 4; ni++) {
                    float* c = acc[mi][ni];
                    mma_tf32(c, al[mi][0], al[mi][1], al[mi][2], al[mi][3],
                             bh[ni][0], bh[ni][1]);
                    mma_tf32(c, ah[mi][0], ah[mi][1], ah[mi][2], ah[mi][3],
                             bl[ni][0], bl[ni][1]);
                    mma_tf32(c, ah[mi][0], ah[mi][1], ah[mi][2], ah[mi][3],
                             bh[ni][0], bh[ni][1]);
                }
        }
    }

    // epilogue: c0 -> (row g, col 2t), c1 -> col 2t+1, c2/c3 -> row+8
    #pragma unroll
    for (int mi = 0; mi < 4; mi++) {
        int row0 = bm + wm * 64 + mi * 16 + g;
        #pragma unroll
        for (int ni = 0; ni < 4; ni++) {
            int col = bn + wn * 32 + ni * 8 + t * 2;
            float b0 = hasBias ? bias[col] : 0.f;
            float b1 = hasBias ? bias[col + 1] : 0.f;
            if (row0 < M) {
                C[(size_t)row0 * EDIM + col]     = acc[mi][ni][0] + b0;
                C[(size_t)row0 * EDIM + col + 1] = acc[mi][ni][1] + b1;
            }
            if (row0 + 8 < M) {
                C[(size_t)(row0 + 8) * EDIM + col]     = acc[mi][ni][2] + b0;
                C[(size_t)(row0 + 8) * EDIM + col + 1] = acc[mi][ni][3] + b1;
            }
        }
    }
}

// ---------------------------------------------------------------------------
// dpt[b,h,j] = sum_s parma[h,s] * K[b, j, h*64+s]
// ---------------------------------------------------------------------------
__global__ void __launch_bounds__(256) dpt_kernel(
    const float* __restrict__ Kt, const float* __restrict__ parma,
    float* __restrict__ dpt)
{
    int idx = blockIdx.x * 256 + threadIdx.x;
    if (idx >= BATCH * HEADS * TLEN) return;
    int j = idx & (TLEN - 1);
    int h = (idx >> 10) & (HEADS - 1);
    int b = idx >> 14;
    const float* kr = Kt + ((size_t)(b * TLEN + j)) * EDIM + h * SDIM;
    const float* pa = parma + h * SDIM;
    float s = 0.f;
    #pragma unroll
    for (int ss = 0; ss < SDIM; ss++) s = fmaf(pa[ss], kr[ss], s);
    dpt[idx] = s;
}

// ---------------------------------------------------------------------------
// cpp[h,p] = sum_s parmb[h,s] * KP[p, h*64+s]
// ---------------------------------------------------------------------------
__global__ void __launch_bounds__(256) cpp_kernel(
    const float* __restrict__ KP, const float* __restrict__ parmb,
    float* __restrict__ cpp)
{
    int idx = blockIdx.x * 256 + threadIdx.x;
    if (idx >= HEADS * P2) return;
    int h = idx / P2;
    int p = idx - h * P2;
    const float* kr = KP + (size_t)p * EDIM + h * SDIM;
    const float* pb = parmb + h * SDIM;
    float s = 0.f;
    #pragma unroll
    for (int ss = 0; ss < SDIM; ss++) s = fmaf(pb[ss], kr[ss], s);
    cpp[idx] = s;
}

// ---------------------------------------------------------------------------
// Attention: one CTA per (b, h, 64-row i-tile); causal loop over 64-col j-tiles.
// scores(i,j) = q_i . (k_j + kp_{i+j}) + dpt[j] + cpp[i+j]; online softmax; P@V.
// ---------------------------------------------------------------------------
#define ATTN_SMEM_FLOATS (64*65 + 64*65 + 64*64 + 64*129 + 64 + 128)

__global__ void __launch_bounds__(256) attn_kernel(
    const float* __restrict__ Q, const float* __restrict__ Kt,
    const float* __restrict__ V, const float* __restrict__ KP,
    const float* __restrict__ dpt, const float* __restrict__ cpp,
    float* __restrict__ O)
{
    extern __shared__ float sm[];
    float* Qs   = sm;                 // [s=64][r=64] pad 65
    float* Ks   = Qs + 64 * 65;      // [s=64][c=64] pad 65
    float* Vs   = Ks + 64 * 65;      // [j=64][s=64]
    float* KPs  = Vs + 64 * 64;      // [s=64][p_local=128] pad 129 (unioned with Ps)
    float* Ps   = KPs;               // [r=64][c=64] pad 65 (reuse after scores done)
    float* dpts = KPs + 64 * 129;    // [64]
    float* cpps = dpts + 64;         // [128]

    const int tid = threadIdx.x;
    const int tx = tid & 15, ty = tid >> 4;
    const int b = blockIdx.z, h = blockIdx.y;
    const int it = (int)gridDim.x - 1 - (int)blockIdx.x;  // big tiles first
    const int I0 = it * 64;
    const size_t headOff = (size_t)h * SDIM;

    for (int idx = tid; idx < 4096; idx += 256) {
        int r = idx >> 6, s = idx & 63;
        Qs[s * 65 + r] = Q[((size_t)(b * TLEN + I0 + r)) * EDIM + headOff + s];
    }

    float m_r[4], l_r[4], o[4][4];
    #pragma unroll
    for (int i = 0; i < 4; i++) {
        m_r[i] = -INFINITY;
        l_r[i] = 0.f;
        #pragma unroll
        for (int j = 0; j < 4; j++) o[i][j] = 0.f;
    }

    for (int jt = 0; jt <= it; jt++) {
        const int J0 = jt * 64;
        const int pbase = I0 + J0;

        for (int idx = tid; idx < 4096; idx += 256) {
            int c = idx >> 6, s = idx & 63;
            size_t g = ((size_t)(b * TLEN + J0 + c)) * EDIM + headOff + s;
            Ks[s * 65 + c] = Kt[g];
            Vs[c * 64 + s] = V[g];
        }
        for (int idx = tid; idx < 8192; idx += 256) {
            int pl = idx >> 6, s = idx & 63;
            int p = pbase + pl;
            KPs[s * 129 + pl] = (p < P2) ? KP[(size_t)p * EDIM + headOff + s] : 0.f;
        }
        if (tid < 64) dpts[tid] = dpt[((size_t)(b * HEADS + h)) * TLEN + J0 + tid];
        if (tid < 128) {
            int p = pbase + tid;
            cpps[tid] = (p < P2) ? cpp[(size_t)h * P2 + p] : 0.f;
        }
        __syncthreads();

        float acc[4][4];
        #pragma unroll
        for (int i = 0; i < 4; i++)
            #pragma unroll
            for (int j = 0; j < 4; j++) acc[i][j] = 0.f;

        #pragma unroll 4
        for (int s = 0; s < 64; s++) {
            float a[4], bk[4], kpv[7];
            #pragma unroll
            for (int i = 0; i < 4; i++) a[i] = Qs[s * 65 + ty + 16 * i];
            #pragma unroll
            for (int j = 0; j < 4; j++) bk[j] = Ks[s * 65 + tx + 16 * j];
            #pragma unroll
            for (int d = 0; d < 7; d++) kpv[d] = KPs[s * 129 + ty + tx + 16 * d];
            #pragma unroll
            for (int i = 0; i < 4; i++)
                #pragma unroll
                for (int j = 0; j < 4; j++)
                    acc[i][j] = fmaf(a[i], bk[j] + kpv[i + j], acc[i][j]);
        }

        #pragma unroll
        for (int i = 0; i < 4; i++) {
            int r = ty + 16 * i;
            float mx = -INFINITY;
            float sc[4];
            #pragma unroll
            for (int j = 0; j < 4; j++) {
                int c = tx + 16 * j;
                float v = acc[i][j] + dpts[c] + cpps[r + c];
                if (J0 + c > I0 + r) v = -1e30f;
                sc[j] = v;
                mx = fmaxf(mx, v);
            }
            #pragma unroll
            for (int off = 8; off >= 1; off >>= 1)
                mx = fmaxf(mx, __shfl_xor_sync(0xffffffffu, mx, off));
            float mnew = fmaxf(m_r[i], mx);
            float scale = __expf(m_r[i] - mnew);
            m_r[i] = mnew;
            float rs = 0.f;
            #pragma unroll
            for (int j = 0; j < 4; j++) {
                float p = __expf(sc[j] - mnew);
                acc[i][j] = p;
                rs += p;
            }
            #pragma unroll
            for (int off = 8; off >= 1; off >>= 1)
                rs += __shfl_xor_sync(0xffffffffu, rs, off);
            l_r[i] = l_r[i] * scale + rs;
            #pragma unroll
            for (int j2 = 0; j2 < 4; j2++) o[i][j2] *= scale;
        }

        __syncthreads();
        #pragma unroll
        for (int i = 0; i < 4; i++)
            #pragma unroll
            for (int j = 0; j < 4; j++)
                Ps[(ty + 16 * i) * 65 + tx + 16 * j] = acc[i][j];
        __syncthreads();

        for (int jj = 0; jj < 64; jj++) {
            float vv[4];
            #pragma unroll
            for (int j2 = 0; j2 < 4; j2++) vv[j2] = Vs[jj * 64 + tx + 16 * j2];
            #pragma unroll
            for (int i = 0; i < 4; i++) {
                float p = Ps[(ty + 16 * i) * 65 + jj];
                #pragma unroll
                for (int j2 = 0; j2 < 4; j2++)
                    o[i][j2] = fmaf(p, vv[j2], o[i][j2]);
            }
        }
        __syncthreads();
    }

    #pragma unroll
    for (int i = 0; i < 4; i++) {
        float inv = 1.f / l_r[i];
        int r = I0 + ty + 16 * i;
        #pragma unroll
        for (int j2 = 0; j2 < 4; j2++)
            O[((size_t)(b * TLEN + r)) * EDIM + headOff + tx + 16 * j2] = o[i][j2] * inv;
    }
}

// ---------------------------------------------------------------------------
// Launch
// ---------------------------------------------------------------------------
extern "C" void kernel_launch(void* const* d_in, const int* in_sizes, int n_in,
                              void* d_out, int out_size)
{
    const float* x     = (const float*)d_in[0];
    const float* Wq    = (const float*)d_in[1];
    const float* Wk    = (const float*)d_in[2];
    const float* Wkp   = (const float*)d_in[3];
    const float* Wv    = (const float*)d_in[4];
    const float* Wu    = (const float*)d_in[5];
    const float* bu    = (const float*)d_in[6];
    const float* parma = (const float*)d_in[7];
    const float* parmb = (const float*)d_in[8];
    const float* pos   = (const float*)d_in[9];
    float* out = (float*)d_out;

    float *Qb, *Kb, *Vb, *KPb, *dptb, *cppb, *ATTb, *Wtb;
    cudaGetSymbolAddress((void**)&Qb,   g_Q);
    cudaGetSymbolAddress((void**)&Kb,   g_K);
    cudaGetSymbolAddress((void**)&Vb,   g_V);
    cudaGetSymbolAddress((void**)&KPb,  g_KP);
    cudaGetSymbolAddress((void**)&dptb, g_dpt);
    cudaGetSymbolAddress((void**)&cppb, g_cpp);
    cudaGetSymbolAddress((void**)&ATTb, g_ATT);
    cudaGetSymbolAddress((void**)&Wtb,  g_Wt);

    const size_t WSZ = (size_t)EDIM * EDIM;
    float* WqT  = Wtb + 0 * WSZ;
    float* WkT  = Wtb + 1 * WSZ;
    float* WvT  = Wtb + 2 * WSZ;
    float* WkpT = Wtb + 3 * WSZ;
    float* WuT  = Wtb + 4 * WSZ;

    dim3 tb(32, 8), tg(32, 32);
    transpose_kernel<<<tg, tb>>>(Wq,  WqT);
    transpose_kernel<<<tg, tb>>>(Wk,  WkT);
    transpose_kernel<<<tg, tb>>>(Wv,  WvT);
    transpose_kernel<<<tg, tb>>>(Wkp, WkpT);
    transpose_kernel<<<tg, tb>>>(Wu,  WuT);

    dim3 gblk(256);
    dim3 g1(EDIM / 128, (BATCH * TLEN) / 128);   // (8, 32)
    tc_gemm_kernel<<<g1, gblk>>>(x, WqT, nullptr, Qb, BATCH * TLEN, 0);
    tc_gemm_kernel<<<g1, gblk>>>(x, WkT, nullptr, Kb, BATCH * TLEN, 0);
    tc_gemm_kernel<<<g1, gblk>>>(x, WvT, nullptr, Vb, BATCH * TLEN, 0);

    dim3 g2(EDIM / 128, (P2 + 127) / 128);       // (8, 16)
    tc_gemm_kernel<<<g2, gblk>>>(pos, WkpT, nullptr, KPb, P2, 0);

    dpt_kernel<<<(BATCH * HEADS * TLEN) / 256, 256>>>(Kb, parma, dptb);
    cpp_kernel<<<(HEADS * P2 + 255) / 256, 256>>>(KPb, parmb, cppb);

    size_t smemBytes = (size_t)ATTN_SMEM_FLOATS * sizeof(float);
    cudaFuncSetAttribute(attn_kernel,
                         cudaFuncAttributeMaxDynamicSharedMemorySize,
                         (int)smemBytes);
    attn_kernel<<<dim3(TLEN / 64, HEADS, BATCH), 256, smemBytes>>>(
        Qb, Kb, Vb, KPb, dptb, cppb, ATTb);

    tc_gemm_kernel<<<g1, gblk>>>(ATTb, WuT, bu, out, BATCH * TLEN, 1);
}

// round 4
// speedup vs baseline: 1.3075x; 1.0049x over previous
#include <cuda_runtime.h>
#include <math.h>
#include <stdint.h>

// Problem constants
#define BATCH 4
#define TLEN  1024
#define EDIM  1024
#define HEADS 16
#define SDIM  64
#define P2    2047   // 2*t - 1

// ---------------------------------------------------------------------------
// Scratch (device globals — no runtime allocation allowed)
// ---------------------------------------------------------------------------
__device__ float g_Q  [(size_t)BATCH * TLEN * EDIM];
__device__ float g_K  [(size_t)BATCH * TLEN * EDIM];
__device__ float g_V  [(size_t)BATCH * TLEN * EDIM];
__device__ float g_KP [(size_t)P2 * EDIM];
__device__ float g_dpt[(size_t)BATCH * HEADS * TLEN];
__device__ float g_cpp[(size_t)HEADS * P2];
__device__ float g_ATT[(size_t)BATCH * TLEN * EDIM];
__device__ float g_Wt [(size_t)5 * EDIM * EDIM];   // transposed weights [N,K]

// ---------------------------------------------------------------------------
// tf32 helpers (baseline PTX — no sm_103a-gated instructions)
// ---------------------------------------------------------------------------
__device__ __forceinline__ uint32_t f2tf32(float x) {
    uint32_t r;
    asm("cvt.rna.tf32.f32 %0, %1;" : "=r"(r) : "f"(x));
    return r;
}
__device__ __forceinline__ void split_tf32(float x, uint32_t& hi, uint32_t& lo) {
    hi = f2tf32(x);
    lo = f2tf32(x - __uint_as_float(hi));
}
__device__ __forceinline__ void mma_tf32(float* c,
    uint32_t a0, uint32_t a1, uint32_t a2, uint32_t a3,
    uint32_t b0, uint32_t b1)
{
    asm volatile(
        "mma.sync.aligned.m16n8k8.row.col.f32.tf32.tf32.f32 "
        "{%0,%1,%2,%3}, {%4,%5,%6,%7}, {%8,%9}, {%0,%1,%2,%3};"
        : "+f"(c[0]), "+f"(c[1]), "+f"(c[2]), "+f"(c[3])
        : "r"(a0), "r"(a1), "r"(a2), "r"(a3), "r"(b0), "r"(b1));
}

// ---------------------------------------------------------------------------
// Weight transpose: dst[N,K] = src[K,N], 1024x1024
// ---------------------------------------------------------------------------
__global__ void __launch_bounds__(256) transpose_kernel(
    const float* __restrict__ src, float* __restrict__ dst)
{
    __shared__ float t[32][33];
    int bx = blockIdx.x * 32, by = blockIdx.y * 32;
    int x = threadIdx.x, y = threadIdx.y;   // block (32, 8)
    #pragma unroll
    for (int i = 0; i < 32; i += 8)
        t[y + i][x] = src[(size_t)(by + y + i) * EDIM + bx + x];
    __syncthreads();
    #pragma unroll
    for (int i = 0; i < 32; i += 8)
        dst[(size_t)(bx + y + i) * EDIM + by + x] = t[x][y + i];
}

// ---------------------------------------------------------------------------
// Tensor-core GEMM (tf32x3): C[M,1024] = A[M,1024] @ Bt[1024,1024]^T (+bias)
// 128x128 CTA tile, BK=32, 256 threads (8 warps, each 64m x 32n),
// m16n8k8 tf32 mma with hi/lo error compensation (3 mma per tile pair).
// ---------------------------------------------------------------------------
#define PADK 36

__global__ void __launch_bounds__(256) tc_gemm_kernel(
    const float* __restrict__ A, const float* __restrict__ Bt,
    const float* __restrict__ bias, float* __restrict__ C,
    int M, int hasBias)
{
    __shared__ float As[128][PADK];
    __shared__ float Bs[128][PADK];

    const int tid  = threadIdx.x;
    const int wid  = tid >> 5;
    const int lane = tid & 31;
    const int wm = wid & 1;          // 0..1 : 64-row slice
    const int wn = wid >> 1;         // 0..3 : 32-col slice
    const int g = lane >> 2;         // group id 0..7
    const int t = lane & 3;          // thread-in-group 0..3
    const int bm = blockIdx.y * 128;
    const int bn = blockIdx.x * 128;

    const float4 f4z = make_float4(0.f, 0.f, 0.f, 0.f);
    float4 ra[4], rb[4];

    #pragma unroll
    for (int r = 0; r < 4; r++) {
        int slot = tid + 256 * r;
        int row = slot >> 3, kc = (slot & 7) * 4;
        int grow = bm + row;
        ra[r] = (grow < M) ? *(const float4*)&A[(size_t)grow * EDIM + kc] : f4z;
        rb[r] = *(const float4*)&Bt[(size_t)(bn + row) * EDIM + kc];
    }

    float acc[4][4][4];
    #pragma unroll
    for (int mi = 0; mi < 4; mi++)
        #pragma unroll
        for (int ni = 0; ni < 4; ni++)
            #pragma unroll
            for (int q = 0; q < 4; q++) acc[mi][ni][q] = 0.f;

    #pragma unroll 1
    for (int kt = 0; kt < 32; kt++) {
        __syncthreads();
        #pragma unroll
        for (int r = 0; r < 4; r++) {
            int slot = tid + 256 * r;
            int row = slot >> 3, kc = (slot & 7) * 4;
            *(float4*)&As[row][kc] = ra[r];
            *(float4*)&Bs[row][kc] = rb[r];
        }
        __syncthreads();

        if (kt + 1 < 32) {
            int koff = (kt + 1) * 32;
            #pragma unroll
            for (int r = 0; r < 4; r++) {
                int slot = tid + 256 * r;
                int row = slot >> 3, kc = (slot & 7) * 4;
                int grow = bm + row;
                ra[r] = (grow < M) ? *(const float4*)&A[(size_t)grow * EDIM + koff + kc] : f4z;
                rb[r] = *(const float4*)&Bt[(size_t)(bn + row) * EDIM + koff + kc];
            }
        }

        #pragma unroll
        for (int kk = 0; kk < 32; kk += 8) {
            uint32_t ah[4][4], al[4][4], bh[4][2], bl[4][2];
            #pragma unroll
            for (int mi = 0; mi < 4; mi++) {
                int r0 = wm * 64 + mi * 16 + g;
                int c0 = kk + t;
                split_tf32(As[r0][c0],         ah[mi][0], al[mi][0]);
                split_tf32(As[r0 + 8][c0],     ah[mi][1], al[mi][1]);
                split_tf32(As[r0][c0 + 4],     ah[mi][2], al[mi][2]);
                split_tf32(As[r0 + 8][c0 + 4], ah[mi][3], al[mi][3]);
            }
            #pragma unroll
            for (int ni = 0; ni < 4; ni++) {
                int rn = wn * 32 + ni * 8 + g;
                split_tf32(Bs[rn][kk + t],     bh[ni][0], bl[ni][0]);
                split_tf32(Bs[rn][kk + t + 4], bh[ni][1], bl[ni][1]);
            }
            #pragma unroll
            for (int mi = 0; mi < 4; mi++)
                #pragma unroll
                for (int ni = 0; ni < 4; ni++) {
                    float* c = acc[mi][ni];
                    mma_tf32(c, al[mi][0], al[mi][1], al[mi][2], al[mi][3],
                             bh[ni][0], bh[ni][1]);
                    mma_tf32(c, ah[mi][0], ah[mi][1], ah[mi][2], ah[mi][3],
                             bl[ni][0], bl[ni][1]);
                    mma_tf32(c, ah[mi][0], ah[mi][1], ah[mi][2], ah[mi][3],
                             bh[ni][0], bh[ni][1]);
                }
        }
    }

    #pragma unroll
    for (int mi = 0; mi < 4; mi++) {
        int row0 = bm + wm * 64 + mi * 16 + g;
        #pragma unroll
        for (int ni = 0; ni < 4; ni++) {
            int col = bn + wn * 32 + ni * 8 + t * 2;
            float b0 = hasBias ? bias[col] : 0.f;
            float b1 = hasBias ? bias[col + 1] : 0.f;
            if (row0 < M) {
                C[(size_t)row0 * EDIM + col]     = acc[mi][ni][0] + b0;
                C[(size_t)row0 * EDIM + col + 1] = acc[mi][ni][1] + b1;
            }
            if (row0 + 8 < M) {
                C[(size_t)(row0 + 8) * EDIM + col]     = acc[mi][ni][2] + b0;
                C[(size_t)(row0 + 8) * EDIM + col + 1] = acc[mi][ni][3] + b1;
            }
        }
    }
}

// ---------------------------------------------------------------------------
// dpt[b,h,j] = sum_s parma[h,s] * K[b, j, h*64+s]
// ---------------------------------------------------------------------------
__global__ void __launch_bounds__(256) dpt_kernel(
    const float* __restrict__ Kt, const float* __restrict__ parma,
    float* __restrict__ dpt)
{
    int idx = blockIdx.x * 256 + threadIdx.x;
    if (idx >= BATCH * HEADS * TLEN) return;
    int j = idx & (TLEN - 1);
    int h = (idx >> 10) & (HEADS - 1);
    int b = idx >> 14;
    const float* kr = Kt + ((size_t)(b * TLEN + j)) * EDIM + h * SDIM;
    const float* pa = parma + h * SDIM;
    float s = 0.f;
    #pragma unroll
    for (int ss = 0; ss < SDIM; ss++) s = fmaf(pa[ss], kr[ss], s);
    dpt[idx] = s;
}

// ---------------------------------------------------------------------------
// cpp[h,p] = sum_s parmb[h,s] * KP[p, h*64+s]
// ---------------------------------------------------------------------------
__global__ void __launch_bounds__(256) cpp_kernel(
    const float* __restrict__ KP, const float* __restrict__ parmb,
    float* __restrict__ cpp)
{
    int idx = blockIdx.x * 256 + threadIdx.x;
    if (idx >= HEADS * P2) return;
    int h = idx / P2;
    int p = idx - h * P2;
    const float* kr = KP + (size_t)p * EDIM + h * SDIM;
    const float* pb = parmb + h * SDIM;
    float s = 0.f;
    #pragma unroll
    for (int ss = 0; ss < SDIM; ss++) s = fmaf(pb[ss], kr[ss], s);
    cpp[idx] = s;
}

// ---------------------------------------------------------------------------
// Tensor-core attention. One CTA per (b,h,64-row i-tile), 256 threads.
// Per j-tile: S[64x192] = Q @ [K ; KPband]^T via tf32x3 mma; fp32 SIMT
// online softmax combining S_K[i][j] + E[i][i+j] + dpt[j] + cpp[i+j];
// O += P @ V via tf32x3 mma with per-row rescale.
// ---------------------------------------------------------------------------
#define AP 68    // padded stride for fragment arrays (conflict-free: 68%32=4)
#define SP 196   // S matrix stride (64 rows x 192 cols)

#define ATTN_SMEM_FLOATS (64*AP + 192*AP + 64*AP + 64*AP + 64 + 128 + 64 + 64)

__global__ void __launch_bounds__(256) attn_kernel(
    const float* __restrict__ Q, const float* __restrict__ Kt,
    const float* __restrict__ V, const float* __restrict__ KP,
    const float* __restrict__ dpt, const float* __restrict__ cpp,
    float* __restrict__ O)
{
    extern __shared__ float sm[];
    float* Qs   = sm;                   // [64][AP]  Q rows (row-major, A frag)
    float* Bs   = Qs + 64 * AP;         // [192][AP] rows 0..63 = K, 64..191 = KP band
    float* Ssm  = Bs;                   // [64][SP]  aliases Bs after scores mma
    float* Vt   = Bs + 192 * AP;        // [64][AP]  Vt[s][j] = V[j][s]
    float* Psm  = Vt + 64 * AP;         // [64][AP]
    float* dpts = Psm + 64 * AP;        // [64]
    float* cpps = dpts + 64;            // [128]
    float* scale_sm = cpps + 128;       // [64]
    float* lsum_sm  = scale_sm + 64;    // [64]

    const int tid  = threadIdx.x;
    const int lane = tid & 31;
    const int wid  = tid >> 5;
    const int g = lane >> 2;            // 0..7
    const int t = lane & 3;             // 0..3
    // scores layout: warp -> m-slice (wid&3)*16, col-half (wid>>2)*96
    const int sm0 = (wid & 3) * 16;
    const int snb = (wid >> 2) * 96;
    // PV layout: warp -> m-slice (wid&3)*16, n-slice (wid>>2)*32
    const int pn0 = (wid >> 2) * 32;
    // softmax layout
    const int tx = tid & 15, ty = tid >> 4;

    const int b = blockIdx.z, h = blockIdx.y;
    const int it = (int)gridDim.x - 1 - (int)blockIdx.x;  // big tiles first
    const int I0 = it * 64;
    const size_t headOff = (size_t)h * SDIM;

    // Stage Q tile once: Qs[r][s]
    for (int idx = tid; idx < 4096; idx += 256) {
        int r = idx >> 6, s = idx & 63;
        Qs[r * AP + s] = Q[((size_t)(b * TLEN + I0 + r)) * EDIM + headOff + s];
    }

    float m_r[4], l_r[4];
    #pragma unroll
    for (int i = 0; i < 4; i++) { m_r[i] = -INFINITY; l_r[i] = 0.f; }
    float o_acc[4][4];
    #pragma unroll
    for (int n = 0; n < 4; n++)
        #pragma unroll
        for (int q = 0; q < 4; q++) o_acc[n][q] = 0.f;

    for (int jt = 0; jt <= it; jt++) {
        const int J0 = jt * 64;
        const int pbase = I0 + J0;

        __syncthreads();   // prev tile's PV reads (Psm/Vt) and Ssm done

        // ---- Stage K rows, KP band, V^T, dpt, cpp ----
        for (int idx = tid; idx < 4096; idx += 256) {
            int c = idx >> 6, s = idx & 63;
            Bs[c * AP + s] = Kt[((size_t)(b * TLEN + J0 + c)) * EDIM + headOff + s];
        }
        for (int idx = tid; idx < 8192; idx += 256) {
            int pl = idx >> 6, s = idx & 63;
            int p = pbase + pl;
            Bs[(64 + pl) * AP + s] = (p < P2) ? KP[(size_t)p * EDIM + headOff + s] : 0.f;
        }
        for (int idx = tid; idx < 4096; idx += 256) {
            int j = idx >> 6, s = idx & 63;
            Vt[s * AP + j] = V[((size_t)(b * TLEN + J0 + j)) * EDIM + headOff + s];
        }
        if (tid < 64) dpts[tid] = dpt[((size_t)(b * HEADS + h)) * TLEN + J0 + tid];
        if (tid < 128) {
            int p = pbase + tid;
            cpps[tid] = (p < P2) ? cpp[(size_t)h * P2 + p] : 0.f;
        }
        __syncthreads();

        // ---- Scores mma: S[64x192] = Q @ Bs^T (tf32x3) ----
        float sacc[12][4];
        #pragma unroll
        for (int n = 0; n < 12; n++)
            #pragma unroll
            for (int q = 0; q < 4; q++) sacc[n][q] = 0.f;

        #pragma unroll
        for (int kk = 0; kk < 64; kk += 8) {
            uint32_t ah[4], al[4];
            split_tf32(Qs[(sm0 + g) * AP + kk + t],         ah[0], al[0]);
            split_tf32(Qs[(sm0 + g + 8) * AP + kk + t],     ah[1], al[1]);
            split_tf32(Qs[(sm0 + g) * AP + kk + t + 4],     ah[2], al[2]);
            split_tf32(Qs[(sm0 + g + 8) * AP + kk + t + 4], ah[3], al[3]);
            #pragma unroll
            for (int nt = 0; nt < 12; nt++) {
                int n0 = snb + nt * 8;
                uint32_t bh0, bl0, bh1, bl1;
                split_tf32(Bs[(n0 + g) * AP + kk + t],     bh0, bl0);
                split_tf32(Bs[(n0 + g) * AP + kk + t + 4], bh1, bl1);
                mma_tf32(sacc[nt], al[0], al[1], al[2], al[3], bh0, bh1);
                mma_tf32(sacc[nt], ah[0], ah[1], ah[2], ah[3], bl0, bl1);
                mma_tf32(sacc[nt], ah[0], ah[1], ah[2], ah[3], bh0, bh1);
            }
        }

        __syncthreads();   // all warps done reading Bs; safe to overwrite as Ssm
        #pragma unroll
        for (int nt = 0; nt < 12; nt++) {
            int n0 = snb + nt * 8 + 2 * t;
            Ssm[(sm0 + g) * SP + n0]         = sacc[nt][0];
            Ssm[(sm0 + g) * SP + n0 + 1]     = sacc[nt][1];
            Ssm[(sm0 + g + 8) * SP + n0]     = sacc[nt][2];
            Ssm[(sm0 + g + 8) * SP + n0 + 1] = sacc[nt][3];
        }
        __syncthreads();

        // ---- Softmax (fp32 SIMT): rows ty+16i, cols tx+16j ----
        #pragma unroll
        for (int i = 0; i < 4; i++) {
            int r = ty + 16 * i;
            float sc[4];
            float mx = -INFINITY;
            #pragma unroll
            for (int j = 0; j < 4; j++) {
                int c = tx + 16 * j;
                float v = Ssm[r * SP + c] + Ssm[r * SP + 64 + r + c]
                        + dpts[c] + cpps[r + c];
                if (J0 + c > I0 + r) v = -1e30f;
                sc[j] = v;
                mx = fmaxf(mx, v);
            }
            #pragma unroll
            for (int off = 8; off >= 1; off >>= 1)
                mx = fmaxf(mx, __shfl_xor_sync(0xffffffffu, mx, off));
            float mnew = fmaxf(m_r[i], mx);
            float scale = __expf(m_r[i] - mnew);
            m_r[i] = mnew;
            float rs = 0.f;
            #pragma unroll
            for (int j = 0; j < 4; j++) {
                float p = __expf(sc[j] - mnew);
                Psm[r * AP + tx + 16 * j] = p;
                rs += p;
            }
            #pragma unroll
            for (int off = 8; off >= 1; off >>= 1)
                rs += __shfl_xor_sync(0xffffffffu, rs, off);
            l_r[i] = l_r[i] * scale + rs;
            if (tx == 0) {
                scale_sm[r] = scale;
                lsum_sm[r]  = l_r[i];
            }
        }
        __syncthreads();

        // ---- PV mma: O = O*scale + P @ V (tf32x3) ----
        const float sA = scale_sm[sm0 + g];
        const float sB = scale_sm[sm0 + g + 8];
        #pragma unroll
        for (int nt = 0; nt < 4; nt++) {
            o_acc[nt][0] *= sA; o_acc[nt][1] *= sA;
            o_acc[nt][2] *= sB; o_acc[nt][3] *= sB;
        }
        #pragma unroll
        for (int kk = 0; kk < 64; kk += 8) {
            uint32_t ah[4], al[4];
            split_tf32(Psm[(sm0 + g) * AP + kk + t],         ah[0], al[0]);
            split_tf32(Psm[(sm0 + g + 8) * AP + kk + t],     ah[1], al[1]);
            split_tf32(Psm[(sm0 + g) * AP + kk + t + 4],     ah[2], al[2]);
            split_tf32(Psm[(sm0 + g + 8) * AP + kk + t + 4], ah[3], al[3]);
            #pragma unroll
            for (int nt = 0; nt < 4; nt++) {
                int n0 = pn0 + nt * 8;
                uint32_t bh0, bl0, bh1, bl1;
                split_tf32(Vt[(n0 + g) * AP + kk + t],     bh0, bl0);
                split_tf32(Vt[(n0 + g) * AP + kk + t + 4], bh1, bl1);
                mma_tf32(o_acc[nt], al[0], al[1], al[2], al[3], bh0, bh1);
                mma_tf32(o_acc[nt], ah[0], ah[1], ah[2], ah[3], bl0, bl1);
                mma_tf32(o_acc[nt], ah[0], ah[1], ah[2], ah[3], bh0, bh1);
            }
        }
    }

    __syncthreads();
    const float invA = 1.f / lsum_sm[sm0 + g];
    const float invB = 1.f / lsum_sm[sm0 + g + 8];
    const size_t row0 = (size_t)(b * TLEN + I0 + sm0 + g) * EDIM;
    const size_t row1 = row0 + 8 * EDIM;
    #pragma unroll
    for (int nt = 0; nt < 4; nt++) {
        size_t col = headOff + pn0 + nt * 8 + 2 * t;
        O[row0 + col]     = o_acc[nt][0] * invA;
        O[row0 + col + 1] = o_acc[nt][1] * invA;
        O[row1 + col]     = o_acc[nt][2] * invB;
        O[row1 + col + 1] = o_acc[nt][3] * invB;
    }
}

// ---------------------------------------------------------------------------
// Launch
// ---------------------------------------------------------------------------
extern "C" void kernel_launch(void* const* d_in, const int* in_sizes, int n_in,
                              void* d_out, int out_size)
{
    const float* x     = (const float*)d_in[0];
    const float* Wq    = (const float*)d_in[1];
    const float* Wk    = (const float*)d_in[2];
    const float* Wkp   = (const float*)d_in[3];
    const float* Wv    = (const float*)d_in[4];
    const float* Wu    = (const float*)d_in[5];
    const float* bu    = (const float*)d_in[6];
    const float* parma = (const float*)d_in[7];
    const float* parmb = (const float*)d_in[8];
    const float* pos   = (const float*)d_in[9];
    float* out = (float*)d_out;

    float *Qb, *Kb, *Vb, *KPb, *dptb, *cppb, *ATTb, *Wtb;
    cudaGetSymbolAddress((void**)&Qb,   g_Q);
    cudaGetSymbolAddress((void**)&Kb,   g_K);
    cudaGetSymbolAddress((void**)&Vb,   g_V);
    cudaGetSymbolAddress((void**)&KPb,  g_KP);
    cudaGetSymbolAddress((void**)&dptb, g_dpt);
    cudaGetSymbolAddress((void**)&cppb, g_cpp);
    cudaGetSymbolAddress((void**)&ATTb, g_ATT);
    cudaGetSymbolAddress((void**)&Wtb,  g_Wt);

    const size_t WSZ = (size_t)EDIM * EDIM;
    float* WqT  = Wtb + 0 * WSZ;
    float* WkT  = Wtb + 1 * WSZ;
    float* WvT  = Wtb + 2 * WSZ;
    float* WkpT = Wtb + 3 * WSZ;
    float* WuT  = Wtb + 4 * WSZ;

    dim3 tb(32, 8), tg(32, 32);
    transpose_kernel<<<tg, tb>>>(Wq,  WqT);
    transpose_kernel<<<tg, tb>>>(Wk,  WkT);
    transpose_kernel<<<tg, tb>>>(Wv,  WvT);
    transpose_kernel<<<tg, tb>>>(Wkp, WkpT);
    transpose_kernel<<<tg, tb>>>(Wu,  WuT);

    dim3 gblk(256);
    dim3 g1(EDIM / 128, (BATCH * TLEN) / 128);   // (8, 32)
    tc_gemm_kernel<<<g1, gblk>>>(x, WqT, nullptr, Qb, BATCH * TLEN, 0);
    tc_gemm_kernel<<<g1, gblk>>>(x, WkT, nullptr, Kb, BATCH * TLEN, 0);
    tc_gemm_kernel<<<g1, gblk>>>(x, WvT, nullptr, Vb, BATCH * TLEN, 0);

    dim3 g2(EDIM / 128, (P2 + 127) / 128);       // (8, 16)
    tc_gemm_kernel<<<g2, gblk>>>(pos, WkpT, nullptr, KPb, P2, 0);

    dpt_kernel<<<(BATCH * HEADS * TLEN) / 256, 256>>>(Kb, parma, dptb);
    cpp_kernel<<<(HEADS * P2 + 255) / 256, 256>>>(KPb, parmb, cppb);

    size_t smemBytes = (size_t)ATTN_SMEM_FLOATS * sizeof(float);
    cudaFuncSetAttribute(attn_kernel,
                         cudaFuncAttributeMaxDynamicSharedMemorySize,
                         (int)smemBytes);
    attn_kernel<<<dim3(TLEN / 64, HEADS, BATCH), 256, smemBytes>>>(
        Qb, Kb, Vb, KPb, dptb, cppb, ATTb);

    tc_gemm_kernel<<<g1, gblk>>>(ATTb, WuT, bu, out, BATCH * TLEN, 1);
}